// round 15
// baseline (speedup 1.0000x reference)
#include <cuda_runtime.h>
#include <cuda_fp16.h>
#include <cstdint>
#include <cstddef>

// ---------------- problem constants ----------------
#define NNODES   100000
#define DFEAT    256
#define MAXDEG   128
#define BATCH    1024
#define FAN1     25
#define FAN2     10
#define OUTD     128           // per-branch output
#define M1       (BATCH*FAN1)          // 25600
#define M2       (BATCH*FAN1*FAN2)     // 256000
#define WSZH     (OUTD * DFEAT / 2)    // half2 words per weight matrix = 16384
#define NB10     (M1 / 4)              // 6400 blocks for mean10
#define NB25     (BATCH / 4)           // 256 blocks for mean25
#define NBG_Z1   (M1 / 64)             // 400 GEMM tiles for z1
#define NBG_Z0   (BATCH / 64)          // 16 GEMM tiles for z0

// ---------------- scratch (device globals; no allocation APIs) ----------------
__device__ int      d_cols1[FAN1];
__device__ int      d_cols2[FAN2];
__device__ int      d_ids1[M1];
__device__ int      d_ids2[M2];
__device__ float    d_m2[M1 * DFEAT];     // mean over fan2 of feats[ids2]
__device__ float    d_z1[M1 * DFEAT];     // layer-1 output for ids1 rows
__device__ float    d_m1[BATCH * DFEAT];  // mean over fan1 of feats[ids1]
__device__ float    d_z0[BATCH * DFEAT];  // layer-1 output for ids rows
__device__ float    d_m3[BATCH * DFEAT];  // mean over fan1 of z1
__device__ uint32_t d_Whh[4 * WSZH];      // fp16 hi of weights, [n][k] half2-packed
__device__ uint32_t d_Wll[4 * WSZH];      // fp16 lo

// ---------------- threefry2x32 (JAX-exact, 20 rounds) ----------------
__device__ __forceinline__ uint32_t rotl32(uint32_t v, int r) {
    return (v << r) | (v >> (32 - r));
}

__device__ __forceinline__ void tf2x32(uint32_t k0, uint32_t k1,
                                       uint32_t x0, uint32_t x1,
                                       uint32_t& y0, uint32_t& y1) {
    uint32_t ks0 = k0, ks1 = k1, ks2 = k0 ^ k1 ^ 0x1BD11BDAu;
    x0 += ks0; x1 += ks1;
    const int r0[4] = {13, 15, 26, 6};
    const int r1[4] = {17, 29, 16, 24};
#define TF_G(RR) { x0 += x1; x1 = rotl32(x1, RR[0]); x1 ^= x0; \
                   x0 += x1; x1 = rotl32(x1, RR[1]); x1 ^= x0; \
                   x0 += x1; x1 = rotl32(x1, RR[2]); x1 ^= x0; \
                   x0 += x1; x1 = rotl32(x1, RR[3]); x1 ^= x0; }
    TF_G(r0); x0 += ks1; x1 += ks2 + 1u;
    TF_G(r1); x0 += ks2; x1 += ks0 + 2u;
    TF_G(r0); x0 += ks0; x1 += ks1 + 3u;
    TF_G(r1); x0 += ks1; x1 += ks2 + 4u;
    TF_G(r0); x0 += ks2; x1 += ks0 + 5u;
#undef TF_G
    y0 = x0; y1 = x1;
}

// jax.random.permutation(k, 128) for k1,k2 = split(key(42)),
// partitionable semantics; random_bits(32) = bits1 ^ bits2 (VERIFIED round 4)
__global__ void setup_perm_kernel() {
    int t = threadIdx.x;  // 128 threads
    uint32_t k1a, k1b, k2a, k2b;
    tf2x32(0u, 42u, 0u, 0u, k1a, k1b);
    tf2x32(0u, 42u, 0u, 1u, k2a, k2b);
    uint32_t s1a, s1b, s2a, s2b;
    tf2x32(k1a, k1b, 0u, 1u, s1a, s1b);
    tf2x32(k2a, k2b, 0u, 1u, s2a, s2b);

    __shared__ uint32_t keys[MAXDEG];
    uint32_t b1, b2;

    tf2x32(s1a, s1b, 0u, (uint32_t)t, b1, b2);
    keys[t] = b1 ^ b2;
    __syncthreads();
    {
        uint32_t me = keys[t];
        int rank = 0;
        #pragma unroll 8
        for (int j = 0; j < MAXDEG; j++) {
            uint32_t kj = keys[j];
            rank += (kj < me) || (kj == me && j < t);
        }
        if (rank < FAN1) d_cols1[rank] = t;
    }
    __syncthreads();

    tf2x32(s2a, s2b, 0u, (uint32_t)t, b1, b2);
    keys[t] = b1 ^ b2;
    __syncthreads();
    {
        uint32_t me = keys[t];
        int rank = 0;
        #pragma unroll 8
        for (int j = 0; j < MAXDEG; j++) {
            uint32_t kj = keys[j];
            rank += (kj < me) || (kj == me && j < t);
        }
        if (rank < FAN2) d_cols2[rank] = t;
    }
}

// Build ids1[B*25] and ids2[B*250]
__global__ void build_ids_kernel(const int* __restrict__ ids,
                                 const int* __restrict__ adj) {
    int i = blockIdx.x * blockDim.x + threadIdx.x;
    if (i >= M1) return;
    int b = i / FAN1, s = i - b * FAN1;
    int id0 = ids[b];
    int id1 = adj[(size_t)id0 * MAXDEG + d_cols1[s]];
    d_ids1[i] = id1;
    const int* arow = adj + (size_t)id1 * MAXDEG;
    #pragma unroll
    for (int j = 0; j < FAN2; j++) {
        d_ids2[(size_t)i * FAN2 + j] = arow[d_cols2[j]];
    }
}

// mean over NS rows of src, 4 rows per block, float4 lanes, ILP-4 accumulators
template <int NS>
__device__ __forceinline__ void mean_body(const float* __restrict__ src,
                                          const int* __restrict__ idx,
                                          float* __restrict__ out, int blk) {
    __shared__ int sidx[4][NS];
    int t = threadIdx.x;
    int row0 = blk * 4;
    if (t < 4 * NS) {
        int rr = t / NS, jj = t - rr * NS;
        sidx[rr][jj] = idx ? idx[(size_t)(row0 + rr) * NS + jj]
                           : (row0 + rr) * NS + jj;
    }
    __syncthreads();
    int rr = t >> 6;
    int c4 = (t & 63) * 4;
    float4 a0 = make_float4(0.f, 0.f, 0.f, 0.f), a1 = a0, a2 = a0, a3 = a0;
    int j = 0;
    #pragma unroll
    for (; j + 4 <= NS; j += 4) {
        const float4 v0 = *(const float4*)(src + (size_t)sidx[rr][j + 0] * DFEAT + c4);
        const float4 v1 = *(const float4*)(src + (size_t)sidx[rr][j + 1] * DFEAT + c4);
        const float4 v2 = *(const float4*)(src + (size_t)sidx[rr][j + 2] * DFEAT + c4);
        const float4 v3 = *(const float4*)(src + (size_t)sidx[rr][j + 3] * DFEAT + c4);
        a0.x += v0.x; a0.y += v0.y; a0.z += v0.z; a0.w += v0.w;
        a1.x += v1.x; a1.y += v1.y; a1.z += v1.z; a1.w += v1.w;
        a2.x += v2.x; a2.y += v2.y; a2.z += v2.z; a2.w += v2.w;
        a3.x += v3.x; a3.y += v3.y; a3.z += v3.z; a3.w += v3.w;
    }
    #pragma unroll
    for (; j < NS; j++) {
        const float4 v0 = *(const float4*)(src + (size_t)sidx[rr][j] * DFEAT + c4);
        a0.x += v0.x; a0.y += v0.y; a0.z += v0.z; a0.w += v0.w;
    }
    const float inv = 1.0f / NS;
    float4 s;
    s.x = (a0.x + a1.x + a2.x + a3.x) * inv;
    s.y = (a0.y + a1.y + a2.y + a3.y) * inv;
    s.z = (a0.z + a1.z + a2.z + a3.z) * inv;
    s.w = (a0.w + a1.w + a2.w + a3.w) * inv;
    *(float4*)(out + (size_t)(row0 + rr) * DFEAT + c4) = s;
}

// merged means; LONG (fan-25) blocks FIRST so they don't form a grid tail
__global__ __launch_bounds__(256)
void means_kernel(const float* __restrict__ feats) {
    if (blockIdx.x < NB25)
        mean_body<FAN1>(feats, d_ids1, d_m1, blockIdx.x);
    else
        mean_body<FAN2>(feats, d_ids2, d_m2, blockIdx.x - NB25);
}

// standalone mean25 of contiguous z1 groups -> m3
__global__ __launch_bounds__(256)
void mean_m3_kernel(const float* __restrict__ z1) {
    mean_body<FAN1>(z1, nullptr, d_m3, blockIdx.x);
}

// one-shot fp16 hi/lo split of the 4 weight matrices, [n][k] half2-packed
__global__ void split_w_kernel(const float* __restrict__ W1x,
                               const float* __restrict__ W1n,
                               const float* __restrict__ W2x,
                               const float* __restrict__ W2n) {
    int m = blockIdx.y;
    const float* W = (m == 0) ? W1x : (m == 1) ? W1n : (m == 2) ? W2x : W2n;
    int i = blockIdx.x * blockDim.x + threadIdx.x;   // half2-pair index
    if (i < WSZH) {
        float w0 = W[2 * i], w1 = W[2 * i + 1];
        __half h0 = __float2half_rn(w0), h1 = __float2half_rn(w1);
        float l0 = w0 - __half2float(h0);
        float l1 = w1 - __half2float(h1);
        __half2 hh = __halves2half2(h0, h1);
        __half2 ll = __floats2half2_rn(l0, l1);
        d_Whh[(size_t)m * WSZH + i] = *(uint32_t*)&hh;
        d_Wll[(size_t)m * WSZH + i] = *(uint32_t*)&ll;
    }
}

#define MMA_F16(d, a0, a1, a2, a3, b0, b1) \
    asm volatile( \
        "mma.sync.aligned.m16n8k16.row.col.f32.f16.f16.f32 " \
        "{%0,%1,%2,%3}, {%4,%5,%6,%7}, {%8,%9}, {%0,%1,%2,%3};" \
        : "+f"((d)[0]), "+f"((d)[1]), "+f"((d)[2]), "+f"((d)[3]) \
        : "r"(a0), "r"(a1), "r"(a2), "r"(a3), "r"(b0), "r"(b1))

#define LDSM_X4(r0, r1, r2, r3, addr) \
    asm volatile( \
        "ldmatrix.sync.aligned.m8n8.x4.shared.b16 {%0,%1,%2,%3}, [%4];" \
        : "=r"(r0), "=r"(r1), "=r"(r2), "=r"(r3) : "r"(addr))

// ---------------- GEMM tile device function (fp16 split, LDSM) ---------------
// C[row, coloff+c] = act( A[row,:] @ W[c,:] + bias[c] ) for a BM x 128 tile.
// A fp32 gathered via gidx (or contiguous). Wh/Wl pre-split fp16 [n][k].
// NPASS = 2 (A-compensated) or 3 (A- and B-compensated).
// smem half2-words, row stride 36 (== 4 mod 32: conflict-free LDSM phases).
#define KCH   64
#define STR   36

template <int WM, int NPASS>
__device__ __forceinline__ void gemm_tile(
    const float* __restrict__ Asrc, const int* __restrict__ gidx,
    const uint32_t* __restrict__ Wh, const uint32_t* __restrict__ Wl,
    const float* __restrict__ bias, float* __restrict__ C,
    int row0, int coloff, int do_relu, uint32_t* smx) {
    constexpr int BM = 32 * WM;
    uint32_t* Ash = smx;
    uint32_t* Asl = smx + BM * STR;
    uint32_t* Bsh = smx + 2 * BM * STR;
    uint32_t* Bsl = smx + 2 * BM * STR + OUTD * STR;   // only valid if NPASS>=3
    __shared__ int rowidx[64];

    int t = threadIdx.x;
    if (t < BM) rowidx[t] = gidx ? gidx[row0 + t] : (row0 + t);
    __syncthreads();

    int wid = t >> 5, lane = t & 31;
    int wm = wid % WM;
    int wn = wid / WM;
    int qp = lane >> 2;
    int qi = lane & 3;
    constexpr int NT = 2 * WM;

    uint32_t ash32 = (uint32_t)__cvta_generic_to_shared(Ash);
    uint32_t asl32 = (uint32_t)__cvta_generic_to_shared(Asl);
    uint32_t bsh32 = (uint32_t)__cvta_generic_to_shared(Bsh);
    uint32_t bsl32 = (uint32_t)__cvta_generic_to_shared(Bsl);
    uint32_t aoffA[2], aoffB;
    #pragma unroll
    for (int mt = 0; mt < 2; mt++)
        aoffA[mt] = (uint32_t)(((wm * 32 + mt * 16 + (lane & 15)) * STR
                                + (lane >> 4) * 4) * 4);
    aoffB = (uint32_t)(((wn * (16 * WM) + (lane >> 4) * 8 + (lane & 7)) * STR
                        + ((lane >> 3) & 1) * 4) * 4);

    float acc[2][NT][4];
    #pragma unroll
    for (int mt = 0; mt < 2; mt++)
        #pragma unroll
        for (int nt = 0; nt < NT; nt++)
            #pragma unroll
            for (int j = 0; j < 4; j++) acc[mt][nt][j] = 0.f;

    for (int kc = 0; kc < 4; kc++) {
        #pragma unroll
        for (int i = 0; i < 2 * WM; i++) {
            int idx = t + i * 256;
            int r  = idx >> 4;
            int k4 = idx & 15;
            const float4 v = *(const float4*)(Asrc + (size_t)rowidx[r] * DFEAT
                                              + kc * KCH + k4 * 4);
            __half2 h01 = __floats2half2_rn(v.x, v.y);
            __half2 h23 = __floats2half2_rn(v.z, v.w);
            float2 f01 = __half22float2(h01);
            float2 f23 = __half22float2(h23);
            __half2 l01 = __floats2half2_rn(v.x - f01.x, v.y - f01.y);
            __half2 l23 = __floats2half2_rn(v.z - f23.x, v.w - f23.y);
            uint2 hw, lw;
            hw.x = *(uint32_t*)&h01; hw.y = *(uint32_t*)&h23;
            lw.x = *(uint32_t*)&l01; lw.y = *(uint32_t*)&l23;
            *(uint2*)(Ash + r * STR + k4 * 2) = hw;
            *(uint2*)(Asl + r * STR + k4 * 2) = lw;
        }
        #pragma unroll
        for (int i = 0; i < 4; i++) {
            int idx = t + i * 256;
            int r  = idx >> 3;
            int w4 = idx & 7;
            *(uint4*)(Bsh + r * STR + w4 * 4) =
                *(const uint4*)(Wh + (size_t)r * (DFEAT / 2) + kc * (KCH / 2) + w4 * 4);
            if (NPASS >= 3)
                *(uint4*)(Bsl + r * STR + w4 * 4) =
                    *(const uint4*)(Wl + (size_t)r * (DFEAT / 2) + kc * (KCH / 2) + w4 * 4);
        }
        __syncthreads();

        #pragma unroll
        for (int kk2 = 0; kk2 < KCH / 2; kk2 += 8) {
            uint32_t kb = (uint32_t)(kk2 * 4);
            uint32_t ah[2][4], al[2][4];
            #pragma unroll
            for (int mt = 0; mt < 2; mt++) {
                LDSM_X4(ah[mt][0], ah[mt][1], ah[mt][2], ah[mt][3],
                        ash32 + aoffA[mt] + kb);
                LDSM_X4(al[mt][0], al[mt][1], al[mt][2], al[mt][3],
                        asl32 + aoffA[mt] + kb);
            }
            #pragma unroll
            for (int p = 0; p < WM; p++) {
                uint32_t pboff = aoffB + (uint32_t)(p * 16 * STR * 4);
                uint32_t bh0, bh1, bh2, bh3;
                LDSM_X4(bh0, bh1, bh2, bh3, bsh32 + pboff + kb);
                #pragma unroll
                for (int mt = 0; mt < 2; mt++) {
                    MMA_F16(acc[mt][2 * p],     ah[mt][0], ah[mt][1], ah[mt][2], ah[mt][3], bh0, bh1);
                    MMA_F16(acc[mt][2 * p],     al[mt][0], al[mt][1], al[mt][2], al[mt][3], bh0, bh1);
                    MMA_F16(acc[mt][2 * p + 1], ah[mt][0], ah[mt][1], ah[mt][2], ah[mt][3], bh2, bh3);
                    MMA_F16(acc[mt][2 * p + 1], al[mt][0], al[mt][1], al[mt][2], al[mt][3], bh2, bh3);
                }
                if (NPASS >= 3) {
                    uint32_t bl0, bl1, bl2, bl3;
                    LDSM_X4(bl0, bl1, bl2, bl3, bsl32 + pboff + kb);
                    #pragma unroll
                    for (int mt = 0; mt < 2; mt++) {
                        MMA_F16(acc[mt][2 * p],     ah[mt][0], ah[mt][1], ah[mt][2], ah[mt][3], bl0, bl1);
                        MMA_F16(acc[mt][2 * p + 1], ah[mt][0], ah[mt][1], ah[mt][2], ah[mt][3], bl2, bl3);
                    }
                }
            }
        }
        __syncthreads();
    }

    #pragma unroll
    for (int nt = 0; nt < NT; nt++) {
        int col = wn * (16 * WM) + nt * 8 + 2 * qi;
        float bx2 = bias[col], by = bias[col + 1];
        #pragma unroll
        for (int mt = 0; mt < 2; mt++) {
            int r0 = row0 + wm * 32 + mt * 16 + qp;
            float v0 = acc[mt][nt][0] + bx2;
            float v1 = acc[mt][nt][1] + by;
            float v2 = acc[mt][nt][2] + bx2;
            float v3 = acc[mt][nt][3] + by;
            if (do_relu) {
                v0 = fmaxf(v0, 0.f); v1 = fmaxf(v1, 0.f);
                v2 = fmaxf(v2, 0.f); v3 = fmaxf(v3, 0.f);
            }
            *(float2*)(C + (size_t)r0 * (2 * OUTD) + coloff + col)       = make_float2(v0, v1);
            *(float2*)(C + (size_t)(r0 + 8) * (2 * OUTD) + coloff + col) = make_float2(v2, v3);
        }
    }
}

// ---- x-branch layer-1 GEMM (no mean dependency): z1 + z0 x-columns
__global__ __launch_bounds__(256, 4)
void x_gemm_kernel(const float* __restrict__ feats,
                   const int* __restrict__ ids,
                   const float* __restrict__ b1x) {
    extern __shared__ uint32_t smx[];
    int bx = blockIdx.x;
    if (bx < NBG_Z1)
        gemm_tile<2, 2>(feats, d_ids1, d_Whh, d_Wll, b1x, d_z1,
                        bx * 64, 0, 1, smx);
    else
        gemm_tile<2, 2>(feats, ids, d_Whh, d_Wll, b1x, d_z0,
                        (bx - NBG_Z1) * 64, 0, 1, smx);
}

// ---- n-branch layer-1 GEMM (consumes m2/m1)
__global__ __launch_bounds__(256, 4)
void l1_n_kernel(const float* __restrict__ b1n) {
    extern __shared__ uint32_t smx[];
    int bx = blockIdx.x;
    if (bx < NBG_Z1)
        gemm_tile<2, 2>(d_m2, nullptr, d_Whh + WSZH, d_Wll + WSZH, b1n, d_z1,
                        bx * 64, OUTD, 1, smx);
    else
        gemm_tile<2, 2>(d_m1, nullptr, d_Whh + WSZH, d_Wll + WSZH, b1n, d_z0,
                        (bx - NBG_Z1) * 64, OUTD, 1, smx);
}

// ---- output layer (both branches via gridDim.y, 3-pass, BM=32)
__global__ __launch_bounds__(256, 3)
void out_kernel(const float* __restrict__ b2x, const float* __restrict__ b2n,
                float* __restrict__ out) {
    extern __shared__ uint32_t smx[];
    int bx = blockIdx.x;
    if (blockIdx.y == 0)
        gemm_tile<1, 3>(d_z0, nullptr, d_Whh + 2 * WSZH, d_Wll + 2 * WSZH,
                        b2x, out, bx * 32, 0, 0, smx);
    else
        gemm_tile<1, 3>(d_m3, nullptr, d_Whh + 3 * WSZH, d_Wll + 3 * WSZH,
                        b2n, out, bx * 32, OUTD, 0, smx);
}

// ---------------- host launcher ----------------
extern "C" void kernel_launch(void* const* d_in, const int* in_sizes, int n_in,
                              void* d_out, int out_size) {
    const int*   ids   = (const int*)d_in[0];
    const int*   adj   = (const int*)d_in[1];
    const float* feats = (const float*)d_in[2];
    const float* W1x   = (const float*)d_in[3];
    const float* b1x   = (const float*)d_in[4];
    const float* W1n   = (const float*)d_in[5];
    const float* b1n   = (const float*)d_in[6];
    const float* W2x   = (const float*)d_in[7];
    const float* b2x   = (const float*)d_in[8];
    const float* W2n   = (const float*)d_in[9];
    const float* b2n   = (const float*)d_in[10];
    float* out = (float*)d_out;

    float* p_z1;
    cudaGetSymbolAddress((void**)&p_z1, d_z1);

    // lazily created side stream + events (host-only resources, created once on
    // the first (non-captured correctness) call; the captured work is identical
    // on every call)
    static cudaStream_t s_side = nullptr;
    static cudaEvent_t ev_fork = nullptr, ev_join = nullptr;
    if (s_side == nullptr) {
        cudaStreamCreateWithFlags(&s_side, cudaStreamNonBlocking);
        cudaEventCreateWithFlags(&ev_fork, cudaEventDisableTiming);
        cudaEventCreateWithFlags(&ev_join, cudaEventDisableTiming);
    }

    const int SMEM_L1  = (2 * 64 * STR + OUTD * STR) * 4;      // 36864 B (NPASS=2)
    const int SMEM_OUT = (2 * 32 * STR + 2 * OUTD * STR) * 4;  // 46080 B (NPASS=3)
    cudaFuncSetAttribute(x_gemm_kernel,
                         cudaFuncAttributeMaxDynamicSharedMemorySize, SMEM_L1);
    cudaFuncSetAttribute(l1_n_kernel,
                         cudaFuncAttributeMaxDynamicSharedMemorySize, SMEM_L1);
    cudaFuncSetAttribute(out_kernel,
                         cudaFuncAttributeMaxDynamicSharedMemorySize, SMEM_OUT);

    // 1. permutations (threefry, partitionable, bits1 ^ bits2)
    setup_perm_kernel<<<1, 128>>>();
    // 2. weight fp16 hi/lo split
    split_w_kernel<<<dim3(WSZH / 256, 4), 256>>>(W1x, W1n, W2x, W2n);
    // 3. neighbor id tables
    build_ids_kernel<<<(M1 + 255) / 256, 256>>>(ids, adj);
    // 4. FORK: means (side stream, high occupancy) || x-branch GEMM (main stream)
    cudaEventRecord(ev_fork, 0);
    cudaStreamWaitEvent(s_side, ev_fork, 0);
    means_kernel<<<NB25 + NB10, 256, 0, s_side>>>(feats);
    cudaEventRecord(ev_join, s_side);
    x_gemm_kernel<<<NBG_Z1 + NBG_Z0, 256, SMEM_L1>>>(feats, ids, b1x);
    // JOIN: main stream waits for means before the n-branch GEMM
    cudaStreamWaitEvent(0, ev_join, 0);
    // 5. n-branch layer-1 GEMM (z1/z0 cols [128,256)), consumes m2/m1
    l1_n_kernel<<<NBG_Z1 + NBG_Z0, 256, SMEM_L1>>>(b1n);
    // 6. m3 = mean25(z1 contiguous groups)
    mean_m3_kernel<<<NB25, 256>>>(p_z1);
    // 7. out = [z0@W2x + b2x | m3@W2n + b2n]  (no relu)
    out_kernel<<<dim3(BATCH / 32, 2), 256, SMEM_OUT>>>(b2x, b2n, out);
}

// round 16
// speedup vs baseline: 1.1037x; 1.1037x over previous
#include <cuda_runtime.h>
#include <cuda_fp16.h>
#include <cstdint>
#include <cstddef>

// ---------------- problem constants ----------------
#define NNODES   100000
#define DFEAT    256
#define MAXDEG   128
#define BATCH    1024
#define FAN1     25
#define FAN2     10
#define OUTD     128           // per-branch output
#define M1       (BATCH*FAN1)          // 25600
#define M2       (BATCH*FAN1*FAN2)     // 256000
#define WSZH     (OUTD * DFEAT / 2)    // half2 words per weight matrix = 16384
#define NB10     (M1 / 8)              // 3200 blocks for mean10 (8 rows/blk)
#define NB25     (BATCH / 8)           // 128 blocks for mean25
#define NBG_Z1   (M1 / 64)             // 400 GEMM tiles for z1
#define NBG_Z0   (BATCH / 64)          // 16 GEMM tiles for z0

// ---------------- scratch (device globals; no allocation APIs) ----------------
__device__ int      d_cols1[FAN1];
__device__ int      d_cols2[FAN2];
__device__ int      d_ids1[M1];
__device__ int      d_ids2[M2];
__device__ float    d_m2[M1 * DFEAT];     // mean over fan2 of feats[ids2]
__device__ float    d_z1[M1 * DFEAT];     // layer-1 output for ids1 rows
__device__ float    d_m1[BATCH * DFEAT];  // mean over fan1 of feats[ids1]
__device__ float    d_z0[BATCH * DFEAT];  // layer-1 output for ids rows
__device__ float    d_m3[BATCH * DFEAT];  // mean over fan1 of z1
__device__ uint32_t d_Whh[4 * WSZH];      // fp16 hi of weights, [n][k] half2-packed
__device__ uint32_t d_Wll[4 * WSZH];      // fp16 lo

// ---------------- threefry2x32 (JAX-exact, 20 rounds) ----------------
__device__ __forceinline__ uint32_t rotl32(uint32_t v, int r) {
    return (v << r) | (v >> (32 - r));
}

__device__ __forceinline__ void tf2x32(uint32_t k0, uint32_t k1,
                                       uint32_t x0, uint32_t x1,
                                       uint32_t& y0, uint32_t& y1) {
    uint32_t ks0 = k0, ks1 = k1, ks2 = k0 ^ k1 ^ 0x1BD11BDAu;
    x0 += ks0; x1 += ks1;
    const int r0[4] = {13, 15, 26, 6};
    const int r1[4] = {17, 29, 16, 24};
#define TF_G(RR) { x0 += x1; x1 = rotl32(x1, RR[0]); x1 ^= x0; \
                   x0 += x1; x1 = rotl32(x1, RR[1]); x1 ^= x0; \
                   x0 += x1; x1 = rotl32(x1, RR[2]); x1 ^= x0; \
                   x0 += x1; x1 = rotl32(x1, RR[3]); x1 ^= x0; }
    TF_G(r0); x0 += ks1; x1 += ks2 + 1u;
    TF_G(r1); x0 += ks2; x1 += ks0 + 2u;
    TF_G(r0); x0 += ks0; x1 += ks1 + 3u;
    TF_G(r1); x0 += ks1; x1 += ks2 + 4u;
    TF_G(r0); x0 += ks2; x1 += ks0 + 5u;
#undef TF_G
    y0 = x0; y1 = x1;
}

// jax.random.permutation(k, 128) for k1,k2 = split(key(42)),
// partitionable semantics; random_bits(32) = bits1 ^ bits2 (VERIFIED round 4)
__global__ void setup_perm_kernel() {
    int t = threadIdx.x;  // 128 threads
    uint32_t k1a, k1b, k2a, k2b;
    tf2x32(0u, 42u, 0u, 0u, k1a, k1b);
    tf2x32(0u, 42u, 0u, 1u, k2a, k2b);
    uint32_t s1a, s1b, s2a, s2b;
    tf2x32(k1a, k1b, 0u, 1u, s1a, s1b);
    tf2x32(k2a, k2b, 0u, 1u, s2a, s2b);

    __shared__ uint32_t keys[MAXDEG];
    uint32_t b1, b2;

    tf2x32(s1a, s1b, 0u, (uint32_t)t, b1, b2);
    keys[t] = b1 ^ b2;
    __syncthreads();
    {
        uint32_t me = keys[t];
        int rank = 0;
        #pragma unroll 8
        for (int j = 0; j < MAXDEG; j++) {
            uint32_t kj = keys[j];
            rank += (kj < me) || (kj == me && j < t);
        }
        if (rank < FAN1) d_cols1[rank] = t;
    }
    __syncthreads();

    tf2x32(s2a, s2b, 0u, (uint32_t)t, b1, b2);
    keys[t] = b1 ^ b2;
    __syncthreads();
    {
        uint32_t me = keys[t];
        int rank = 0;
        #pragma unroll 8
        for (int j = 0; j < MAXDEG; j++) {
            uint32_t kj = keys[j];
            rank += (kj < me) || (kj == me && j < t);
        }
        if (rank < FAN2) d_cols2[rank] = t;
    }
}

// Build ids1[B*25] and ids2[B*250]
__global__ void build_ids_kernel(const int* __restrict__ ids,
                                 const int* __restrict__ adj) {
    int i = blockIdx.x * blockDim.x + threadIdx.x;
    if (i >= M1) return;
    int b = i / FAN1, s = i - b * FAN1;
    int id0 = ids[b];
    int id1 = adj[(size_t)id0 * MAXDEG + d_cols1[s]];
    d_ids1[i] = id1;
    const int* arow = adj + (size_t)id1 * MAXDEG;
    #pragma unroll
    for (int j = 0; j < FAN2; j++) {
        d_ids2[(size_t)i * FAN2 + j] = arow[d_cols2[j]];
    }
}

// mean over NS rows of src, 8 rows per block, each thread owns two row-halves
// (cols c4 and c4+128), 2-way j-unroll -> 4 independent accumulator chains.
template <int NS>
__device__ __forceinline__ void mean_body8(const float* __restrict__ src,
                                           const int* __restrict__ idx,
                                           float* __restrict__ out, int blk) {
    __shared__ int sidx[8][NS];
    int t = threadIdx.x;
    int row0 = blk * 8;
    if (t < 8 * NS) {
        int rr = t / NS, jj = t - rr * NS;
        sidx[rr][jj] = idx ? idx[(size_t)(row0 + rr) * NS + jj]
                           : (row0 + rr) * NS + jj;
    }
    __syncthreads();
    int rr = t >> 5;
    int c4 = (t & 31) * 4;           // half0 col; half1 col = c4 + 128
    float4 a00 = make_float4(0.f, 0.f, 0.f, 0.f);
    float4 a01 = a00, a10 = a00, a11 = a00;
    int j = 0;
    #pragma unroll
    for (; j + 2 <= NS; j += 2) {
        const float* r0 = src + (size_t)sidx[rr][j] * DFEAT;
        const float* r1 = src + (size_t)sidx[rr][j + 1] * DFEAT;
        const float4 v00 = *(const float4*)(r0 + c4);
        const float4 v01 = *(const float4*)(r0 + c4 + 128);
        const float4 v10 = *(const float4*)(r1 + c4);
        const float4 v11 = *(const float4*)(r1 + c4 + 128);
        a00.x += v00.x; a00.y += v00.y; a00.z += v00.z; a00.w += v00.w;
        a01.x += v01.x; a01.y += v01.y; a01.z += v01.z; a01.w += v01.w;
        a10.x += v10.x; a10.y += v10.y; a10.z += v10.z; a10.w += v10.w;
        a11.x += v11.x; a11.y += v11.y; a11.z += v11.z; a11.w += v11.w;
    }
    if (j < NS) {
        const float* r0 = src + (size_t)sidx[rr][j] * DFEAT;
        const float4 v00 = *(const float4*)(r0 + c4);
        const float4 v01 = *(const float4*)(r0 + c4 + 128);
        a00.x += v00.x; a00.y += v00.y; a00.z += v00.z; a00.w += v00.w;
        a01.x += v01.x; a01.y += v01.y; a01.z += v01.z; a01.w += v01.w;
    }
    const float inv = 1.0f / NS;
    float4 s0, s1;
    s0.x = (a00.x + a10.x) * inv; s0.y = (a00.y + a10.y) * inv;
    s0.z = (a00.z + a10.z) * inv; s0.w = (a00.w + a10.w) * inv;
    s1.x = (a01.x + a11.x) * inv; s1.y = (a01.y + a11.y) * inv;
    s1.z = (a01.z + a11.z) * inv; s1.w = (a01.w + a11.w) * inv;
    float* orow = out + (size_t)(row0 + rr) * DFEAT;
    *(float4*)(orow + c4)       = s0;
    *(float4*)(orow + c4 + 128) = s1;
}

// one-shot fp16 hi/lo split of the 4 weight matrices, [n][k] half2-packed
__global__ void split_w_kernel(const float* __restrict__ W1x,
                               const float* __restrict__ W1n,
                               const float* __restrict__ W2x,
                               const float* __restrict__ W2n) {
    int m = blockIdx.y;
    const float* W = (m == 0) ? W1x : (m == 1) ? W1n : (m == 2) ? W2x : W2n;
    int i = blockIdx.x * blockDim.x + threadIdx.x;   // half2-pair index
    if (i < WSZH) {
        float w0 = W[2 * i], w1 = W[2 * i + 1];
        __half h0 = __float2half_rn(w0), h1 = __float2half_rn(w1);
        float l0 = w0 - __half2float(h0);
        float l1 = w1 - __half2float(h1);
        __half2 hh = __halves2half2(h0, h1);
        __half2 ll = __floats2half2_rn(l0, l1);
        d_Whh[(size_t)m * WSZH + i] = *(uint32_t*)&hh;
        d_Wll[(size_t)m * WSZH + i] = *(uint32_t*)&ll;
    }
}

#define MMA_F16(d, a0, a1, a2, a3, b0, b1) \
    asm volatile( \
        "mma.sync.aligned.m16n8k16.row.col.f32.f16.f16.f32 " \
        "{%0,%1,%2,%3}, {%4,%5,%6,%7}, {%8,%9}, {%0,%1,%2,%3};" \
        : "+f"((d)[0]), "+f"((d)[1]), "+f"((d)[2]), "+f"((d)[3]) \
        : "r"(a0), "r"(a1), "r"(a2), "r"(a3), "r"(b0), "r"(b1))

#define LDSM_X4(r0, r1, r2, r3, addr) \
    asm volatile( \
        "ldmatrix.sync.aligned.m8n8.x4.shared.b16 {%0,%1,%2,%3}, [%4];" \
        : "=r"(r0), "=r"(r1), "=r"(r2), "=r"(r3) : "r"(addr))

// ---------------- GEMM tile device function (fp16 split, LDSM) ---------------
#define KCH   64
#define STR   36

template <int WM, int NPASS>
__device__ __forceinline__ void gemm_tile(
    const float* __restrict__ Asrc, const int* __restrict__ gidx,
    const uint32_t* __restrict__ Wh, const uint32_t* __restrict__ Wl,
    const float* __restrict__ bias, float* __restrict__ C,
    int row0, int coloff, int do_relu, uint32_t* smx) {
    constexpr int BM = 32 * WM;
    uint32_t* Ash = smx;
    uint32_t* Asl = smx + BM * STR;
    uint32_t* Bsh = smx + 2 * BM * STR;
    uint32_t* Bsl = smx + 2 * BM * STR + OUTD * STR;   // only valid if NPASS>=3
    __shared__ int rowidx[64];

    int t = threadIdx.x;
    if (t < BM) rowidx[t] = gidx ? gidx[row0 + t] : (row0 + t);
    __syncthreads();

    int wid = t >> 5, lane = t & 31;
    int wm = wid % WM;
    int wn = wid / WM;
    int qp = lane >> 2;
    int qi = lane & 3;
    constexpr int NT = 2 * WM;

    uint32_t ash32 = (uint32_t)__cvta_generic_to_shared(Ash);
    uint32_t asl32 = (uint32_t)__cvta_generic_to_shared(Asl);
    uint32_t bsh32 = (uint32_t)__cvta_generic_to_shared(Bsh);
    uint32_t bsl32 = (uint32_t)__cvta_generic_to_shared(Bsl);
    uint32_t aoffA[2], aoffB;
    #pragma unroll
    for (int mt = 0; mt < 2; mt++)
        aoffA[mt] = (uint32_t)(((wm * 32 + mt * 16 + (lane & 15)) * STR
                                + (lane >> 4) * 4) * 4);
    aoffB = (uint32_t)(((wn * (16 * WM) + (lane >> 4) * 8 + (lane & 7)) * STR
                        + ((lane >> 3) & 1) * 4) * 4);

    float acc[2][NT][4];
    #pragma unroll
    for (int mt = 0; mt < 2; mt++)
        #pragma unroll
        for (int nt = 0; nt < NT; nt++)
            #pragma unroll
            for (int j = 0; j < 4; j++) acc[mt][nt][j] = 0.f;

    for (int kc = 0; kc < 4; kc++) {
        #pragma unroll
        for (int i = 0; i < 2 * WM; i++) {
            int idx = t + i * 256;
            int r  = idx >> 4;
            int k4 = idx & 15;
            const float4 v = *(const float4*)(Asrc + (size_t)rowidx[r] * DFEAT
                                              + kc * KCH + k4 * 4);
            __half2 h01 = __floats2half2_rn(v.x, v.y);
            __half2 h23 = __floats2half2_rn(v.z, v.w);
            float2 f01 = __half22float2(h01);
            float2 f23 = __half22float2(h23);
            __half2 l01 = __floats2half2_rn(v.x - f01.x, v.y - f01.y);
            __half2 l23 = __floats2half2_rn(v.z - f23.x, v.w - f23.y);
            uint2 hw, lw;
            hw.x = *(uint32_t*)&h01; hw.y = *(uint32_t*)&h23;
            lw.x = *(uint32_t*)&l01; lw.y = *(uint32_t*)&l23;
            *(uint2*)(Ash + r * STR + k4 * 2) = hw;
            *(uint2*)(Asl + r * STR + k4 * 2) = lw;
        }
        #pragma unroll
        for (int i = 0; i < 4; i++) {
            int idx = t + i * 256;
            int r  = idx >> 3;
            int w4 = idx & 7;
            *(uint4*)(Bsh + r * STR + w4 * 4) =
                *(const uint4*)(Wh + (size_t)r * (DFEAT / 2) + kc * (KCH / 2) + w4 * 4);
            if (NPASS >= 3)
                *(uint4*)(Bsl + r * STR + w4 * 4) =
                    *(const uint4*)(Wl + (size_t)r * (DFEAT / 2) + kc * (KCH / 2) + w4 * 4);
        }
        __syncthreads();

        #pragma unroll
        for (int kk2 = 0; kk2 < KCH / 2; kk2 += 8) {
            uint32_t kb = (uint32_t)(kk2 * 4);
            uint32_t ah[2][4], al[2][4];
            #pragma unroll
            for (int mt = 0; mt < 2; mt++) {
                LDSM_X4(ah[mt][0], ah[mt][1], ah[mt][2], ah[mt][3],
                        ash32 + aoffA[mt] + kb);
                LDSM_X4(al[mt][0], al[mt][1], al[mt][2], al[mt][3],
                        asl32 + aoffA[mt] + kb);
            }
            #pragma unroll
            for (int p = 0; p < WM; p++) {
                uint32_t pboff = aoffB + (uint32_t)(p * 16 * STR * 4);
                uint32_t bh0, bh1, bh2, bh3;
                LDSM_X4(bh0, bh1, bh2, bh3, bsh32 + pboff + kb);
                #pragma unroll
                for (int mt = 0; mt < 2; mt++) {
                    MMA_F16(acc[mt][2 * p],     ah[mt][0], ah[mt][1], ah[mt][2], ah[mt][3], bh0, bh1);
                    MMA_F16(acc[mt][2 * p],     al[mt][0], al[mt][1], al[mt][2], al[mt][3], bh0, bh1);
                    MMA_F16(acc[mt][2 * p + 1], ah[mt][0], ah[mt][1], ah[mt][2], ah[mt][3], bh2, bh3);
                    MMA_F16(acc[mt][2 * p + 1], al[mt][0], al[mt][1], al[mt][2], al[mt][3], bh2, bh3);
                }
                if (NPASS >= 3) {
                    uint32_t bl0, bl1, bl2, bl3;
                    LDSM_X4(bl0, bl1, bl2, bl3, bsl32 + pboff + kb);
                    #pragma unroll
                    for (int mt = 0; mt < 2; mt++) {
                        MMA_F16(acc[mt][2 * p],     ah[mt][0], ah[mt][1], ah[mt][2], ah[mt][3], bl0, bl1);
                        MMA_F16(acc[mt][2 * p + 1], ah[mt][0], ah[mt][1], ah[mt][2], ah[mt][3], bl2, bl3);
                    }
                }
            }
        }
        __syncthreads();
    }

    #pragma unroll
    for (int nt = 0; nt < NT; nt++) {
        int col = wn * (16 * WM) + nt * 8 + 2 * qi;
        float bx2 = bias[col], by = bias[col + 1];
        #pragma unroll
        for (int mt = 0; mt < 2; mt++) {
            int r0 = row0 + wm * 32 + mt * 16 + qp;
            float v0 = acc[mt][nt][0] + bx2;
            float v1 = acc[mt][nt][1] + by;
            float v2 = acc[mt][nt][2] + bx2;
            float v3 = acc[mt][nt][3] + by;
            if (do_relu) {
                v0 = fmaxf(v0, 0.f); v1 = fmaxf(v1, 0.f);
                v2 = fmaxf(v2, 0.f); v3 = fmaxf(v3, 0.f);
            }
            *(float2*)(C + (size_t)r0 * (2 * OUTD) + coloff + col)       = make_float2(v0, v1);
            *(float2*)(C + (size_t)(r0 + 8) * (2 * OUTD) + coloff + col) = make_float2(v2, v3);
        }
    }
}

// ---- fused launch: x-branch layer-1 GEMM (no mean dependency) + all means
// blocks [0,400): z1 x-tiles | [400,416): z0 x-tiles | [416,544): mean25 -> m1
// | [544,3744): mean10 -> m2.
__global__ __launch_bounds__(256, 4)
void fused_x_means_kernel(const float* __restrict__ feats,
                          const int* __restrict__ ids,
                          const float* __restrict__ b1x) {
    extern __shared__ uint32_t smx[];
    int bx = blockIdx.x;
    if (bx < NBG_Z1) {
        gemm_tile<2, 2>(feats, d_ids1, d_Whh, d_Wll, b1x, d_z1,
                        bx * 64, 0, 1, smx);
    } else if (bx < NBG_Z1 + NBG_Z0) {
        gemm_tile<2, 2>(feats, ids, d_Whh, d_Wll, b1x, d_z0,
                        (bx - NBG_Z1) * 64, 0, 1, smx);
    } else if (bx < NBG_Z1 + NBG_Z0 + NB25) {
        mean_body8<FAN1>(feats, d_ids1, d_m1, bx - NBG_Z1 - NBG_Z0);
    } else {
        mean_body8<FAN2>(feats, d_ids2, d_m2, bx - NBG_Z1 - NBG_Z0 - NB25);
    }
}

// ---- n-branch layer-1 GEMM (consumes m2/m1)
__global__ __launch_bounds__(256, 4)
void l1_n_kernel(const float* __restrict__ b1n) {
    extern __shared__ uint32_t smx[];
    int bx = blockIdx.x;
    if (bx < NBG_Z1)
        gemm_tile<2, 2>(d_m2, nullptr, d_Whh + WSZH, d_Wll + WSZH, b1n, d_z1,
                        bx * 64, OUTD, 1, smx);
    else
        gemm_tile<2, 2>(d_m1, nullptr, d_Whh + WSZH, d_Wll + WSZH, b1n, d_z0,
                        (bx - NBG_Z1) * 64, OUTD, 1, smx);
}

// ---- merged m3 means + out-layer x-branch (both depend only on l1_n)
__global__ __launch_bounds__(256, 3)
void m3_outx_kernel(const float* __restrict__ b2x, float* __restrict__ out) {
    extern __shared__ uint32_t smx[];
    int bx = blockIdx.x;
    if (bx < NB25)
        mean_body8<FAN1>(d_z1, nullptr, d_m3, bx);
    else
        gemm_tile<1, 3>(d_z0, nullptr, d_Whh + 2 * WSZH, d_Wll + 2 * WSZH,
                        b2x, out, (bx - NB25) * 32, 0, 0, smx);
}

// ---- out-layer n-branch (consumes m3)
__global__ __launch_bounds__(256, 3)
void out_n_kernel(const float* __restrict__ b2n, float* __restrict__ out) {
    extern __shared__ uint32_t smx[];
    gemm_tile<1, 3>(d_m3, nullptr, d_Whh + 3 * WSZH, d_Wll + 3 * WSZH,
                    b2n, out, blockIdx.x * 32, OUTD, 0, smx);
}

// ---------------- host launcher ----------------
extern "C" void kernel_launch(void* const* d_in, const int* in_sizes, int n_in,
                              void* d_out, int out_size) {
    const int*   ids   = (const int*)d_in[0];
    const int*   adj   = (const int*)d_in[1];
    const float* feats = (const float*)d_in[2];
    const float* W1x   = (const float*)d_in[3];
    const float* b1x   = (const float*)d_in[4];
    const float* W1n   = (const float*)d_in[5];
    const float* b1n   = (const float*)d_in[6];
    const float* W2x   = (const float*)d_in[7];
    const float* b2x   = (const float*)d_in[8];
    const float* W2n   = (const float*)d_in[9];
    const float* b2n   = (const float*)d_in[10];
    float* out = (float*)d_out;

    const int SMEM_L1  = (2 * 64 * STR + OUTD * STR) * 4;      // 36864 B (NPASS=2)
    const int SMEM_OUT = (2 * 32 * STR + 2 * OUTD * STR) * 4;  // 46080 B (NPASS=3)
    cudaFuncSetAttribute(fused_x_means_kernel,
                         cudaFuncAttributeMaxDynamicSharedMemorySize, SMEM_L1);
    cudaFuncSetAttribute(l1_n_kernel,
                         cudaFuncAttributeMaxDynamicSharedMemorySize, SMEM_L1);
    cudaFuncSetAttribute(m3_outx_kernel,
                         cudaFuncAttributeMaxDynamicSharedMemorySize, SMEM_OUT);
    cudaFuncSetAttribute(out_n_kernel,
                         cudaFuncAttributeMaxDynamicSharedMemorySize, SMEM_OUT);

    // 1. permutations (threefry, partitionable, bits1 ^ bits2)
    setup_perm_kernel<<<1, 128>>>();
    // 2. weight fp16 hi/lo split
    split_w_kernel<<<dim3(WSZH / 256, 4), 256>>>(W1x, W1n, W2x, W2n);
    // 3. neighbor id tables
    build_ids_kernel<<<(M1 + 255) / 256, 256>>>(ids, adj);
    // 4. FUSED: x-branch layer-1 GEMM + m1 + m2 means (8-row ILP-4 bodies)
    fused_x_means_kernel<<<NBG_Z1 + NBG_Z0 + NB25 + NB10, 256, SMEM_L1>>>(
        feats, ids, b1x);
    // 5. n-branch layer-1 GEMM (z1/z0 cols [128,256)), consumes m2/m1
    l1_n_kernel<<<NBG_Z1 + NBG_Z0, 256, SMEM_L1>>>(b1n);
    // 6. MERGED: m3 = mean25(z1 groups) + out-layer x-branch (z0@W2x)
    m3_outx_kernel<<<NB25 + BATCH / 32, 256, SMEM_OUT>>>(b2x, out);
    // 7. out-layer n-branch: out cols [128,256) = m3@W2n + b2n
    out_n_kernel<<<BATCH / 32, 256, SMEM_OUT>>>(b2n, out);
}

// round 17
// speedup vs baseline: 1.1596x; 1.0507x over previous
#include <cuda_runtime.h>
#include <cuda_fp16.h>
#include <cstdint>
#include <cstddef>

// ---------------- problem constants ----------------
#define NNODES   100000
#define DFEAT    256
#define MAXDEG   128
#define BATCH    1024
#define FAN1     25
#define FAN2     10
#define OUTD     128           // per-branch output
#define M1       (BATCH*FAN1)          // 25600
#define M2       (BATCH*FAN1*FAN2)     // 256000
#define WSZH     (OUTD * DFEAT / 2)    // half2 words per weight matrix = 16384
#define NB10     (M1 / 8)              // 3200 blocks for mean10 (8 rows/blk)
#define NB25     (BATCH / 8)           // 128 blocks for mean25
#define NBG_Z1   (M1 / 64)             // 400 GEMM tiles for z1
#define NBG_Z0   (BATCH / 64)          // 16 GEMM tiles for z0

// ---------------- scratch (device globals; no allocation APIs) ----------------
__device__ int      d_cols1[FAN1];
__device__ int      d_cols2[FAN2];
__device__ int      d_ids1[M1];
__device__ int      d_ids2[M2];
__device__ float    d_m2[M1 * DFEAT];     // mean over fan2 of feats[ids2]
__device__ float    d_z1[M1 * DFEAT];     // layer-1 output for ids1 rows
__device__ float    d_m1[BATCH * DFEAT];  // mean over fan1 of feats[ids1]
__device__ float    d_z0[BATCH * DFEAT];  // layer-1 output for ids rows
__device__ float    d_m3[BATCH * DFEAT];  // mean over fan1 of z1
__device__ uint32_t d_Whh[4 * WSZH];      // fp16 hi of weights, [n][k] half2-packed
__device__ uint32_t d_Wll[4 * WSZH];      // fp16 lo

// ---------------- threefry2x32 (JAX-exact, 20 rounds) ----------------
__device__ __forceinline__ uint32_t rotl32(uint32_t v, int r) {
    return (v << r) | (v >> (32 - r));
}

__device__ __forceinline__ void tf2x32(uint32_t k0, uint32_t k1,
                                       uint32_t x0, uint32_t x1,
                                       uint32_t& y0, uint32_t& y1) {
    uint32_t ks0 = k0, ks1 = k1, ks2 = k0 ^ k1 ^ 0x1BD11BDAu;
    x0 += ks0; x1 += ks1;
    const int r0[4] = {13, 15, 26, 6};
    const int r1[4] = {17, 29, 16, 24};
#define TF_G(RR) { x0 += x1; x1 = rotl32(x1, RR[0]); x1 ^= x0; \
                   x0 += x1; x1 = rotl32(x1, RR[1]); x1 ^= x0; \
                   x0 += x1; x1 = rotl32(x1, RR[2]); x1 ^= x0; \
                   x0 += x1; x1 = rotl32(x1, RR[3]); x1 ^= x0; }
    TF_G(r0); x0 += ks1; x1 += ks2 + 1u;
    TF_G(r1); x0 += ks2; x1 += ks0 + 2u;
    TF_G(r0); x0 += ks0; x1 += ks1 + 3u;
    TF_G(r1); x0 += ks1; x1 += ks2 + 4u;
    TF_G(r0); x0 += ks2; x1 += ks0 + 5u;
#undef TF_G
    y0 = x0; y1 = x1;
}

// jax.random.permutation(k, 128) for k1,k2 = split(key(42)),
// partitionable semantics; random_bits(32) = bits1 ^ bits2 (VERIFIED round 4)
__global__ void setup_perm_kernel() {
    int t = threadIdx.x;  // 128 threads
    uint32_t k1a, k1b, k2a, k2b;
    tf2x32(0u, 42u, 0u, 0u, k1a, k1b);
    tf2x32(0u, 42u, 0u, 1u, k2a, k2b);
    uint32_t s1a, s1b, s2a, s2b;
    tf2x32(k1a, k1b, 0u, 1u, s1a, s1b);
    tf2x32(k2a, k2b, 0u, 1u, s2a, s2b);

    __shared__ uint32_t keys[MAXDEG];
    uint32_t b1, b2;

    tf2x32(s1a, s1b, 0u, (uint32_t)t, b1, b2);
    keys[t] = b1 ^ b2;
    __syncthreads();
    {
        uint32_t me = keys[t];
        int rank = 0;
        #pragma unroll 8
        for (int j = 0; j < MAXDEG; j++) {
            uint32_t kj = keys[j];
            rank += (kj < me) || (kj == me && j < t);
        }
        if (rank < FAN1) d_cols1[rank] = t;
    }
    __syncthreads();

    tf2x32(s2a, s2b, 0u, (uint32_t)t, b1, b2);
    keys[t] = b1 ^ b2;
    __syncthreads();
    {
        uint32_t me = keys[t];
        int rank = 0;
        #pragma unroll 8
        for (int j = 0; j < MAXDEG; j++) {
            uint32_t kj = keys[j];
            rank += (kj < me) || (kj == me && j < t);
        }
        if (rank < FAN2) d_cols2[rank] = t;
    }
}

// Build ids1[B*25] and ids2[B*250]
__global__ void build_ids_kernel(const int* __restrict__ ids,
                                 const int* __restrict__ adj) {
    int i = blockIdx.x * blockDim.x + threadIdx.x;
    if (i >= M1) return;
    int b = i / FAN1, s = i - b * FAN1;
    int id0 = ids[b];
    int id1 = adj[(size_t)id0 * MAXDEG + d_cols1[s]];
    d_ids1[i] = id1;
    const int* arow = adj + (size_t)id1 * MAXDEG;
    #pragma unroll
    for (int j = 0; j < FAN2; j++) {
        d_ids2[(size_t)i * FAN2 + j] = arow[d_cols2[j]];
    }
}

// mean over NS rows of src, 8 rows per block, each thread owns two row-halves
// (cols c4 and c4+128), 2-way j-unroll -> 4 independent accumulator chains.
template <int NS>
__device__ __forceinline__ void mean_body8(const float* __restrict__ src,
                                           const int* __restrict__ idx,
                                           float* __restrict__ out, int blk) {
    __shared__ int sidx[8][NS];
    int t = threadIdx.x;
    int row0 = blk * 8;
    if (t < 8 * NS) {
        int rr = t / NS, jj = t - rr * NS;
        sidx[rr][jj] = idx ? idx[(size_t)(row0 + rr) * NS + jj]
                           : (row0 + rr) * NS + jj;
    }
    __syncthreads();
    int rr = t >> 5;
    int c4 = (t & 31) * 4;           // half0 col; half1 col = c4 + 128
    float4 a00 = make_float4(0.f, 0.f, 0.f, 0.f);
    float4 a01 = a00, a10 = a00, a11 = a00;
    int j = 0;
    #pragma unroll
    for (; j + 2 <= NS; j += 2) {
        const float* r0 = src + (size_t)sidx[rr][j] * DFEAT;
        const float* r1 = src + (size_t)sidx[rr][j + 1] * DFEAT;
        const float4 v00 = *(const float4*)(r0 + c4);
        const float4 v01 = *(const float4*)(r0 + c4 + 128);
        const float4 v10 = *(const float4*)(r1 + c4);
        const float4 v11 = *(const float4*)(r1 + c4 + 128);
        a00.x += v00.x; a00.y += v00.y; a00.z += v00.z; a00.w += v00.w;
        a01.x += v01.x; a01.y += v01.y; a01.z += v01.z; a01.w += v01.w;
        a10.x += v10.x; a10.y += v10.y; a10.z += v10.z; a10.w += v10.w;
        a11.x += v11.x; a11.y += v11.y; a11.z += v11.z; a11.w += v11.w;
    }
    if (j < NS) {
        const float* r0 = src + (size_t)sidx[rr][j] * DFEAT;
        const float4 v00 = *(const float4*)(r0 + c4);
        const float4 v01 = *(const float4*)(r0 + c4 + 128);
        a00.x += v00.x; a00.y += v00.y; a00.z += v00.z; a00.w += v00.w;
        a01.x += v01.x; a01.y += v01.y; a01.z += v01.z; a01.w += v01.w;
    }
    const float inv = 1.0f / NS;
    float4 s0, s1;
    s0.x = (a00.x + a10.x) * inv; s0.y = (a00.y + a10.y) * inv;
    s0.z = (a00.z + a10.z) * inv; s0.w = (a00.w + a10.w) * inv;
    s1.x = (a01.x + a11.x) * inv; s1.y = (a01.y + a11.y) * inv;
    s1.z = (a01.z + a11.z) * inv; s1.w = (a01.w + a11.w) * inv;
    float* orow = out + (size_t)(row0 + rr) * DFEAT;
    *(float4*)(orow + c4)       = s0;
    *(float4*)(orow + c4 + 128) = s1;
}

// one-shot fp16 hi/lo split of the 4 weight matrices, [n][k] half2-packed
__global__ void split_w_kernel(const float* __restrict__ W1x,
                               const float* __restrict__ W1n,
                               const float* __restrict__ W2x,
                               const float* __restrict__ W2n) {
    int m = blockIdx.y;
    const float* W = (m == 0) ? W1x : (m == 1) ? W1n : (m == 2) ? W2x : W2n;
    int i = blockIdx.x * blockDim.x + threadIdx.x;   // half2-pair index
    if (i < WSZH) {
        float w0 = W[2 * i], w1 = W[2 * i + 1];
        __half h0 = __float2half_rn(w0), h1 = __float2half_rn(w1);
        float l0 = w0 - __half2float(h0);
        float l1 = w1 - __half2float(h1);
        __half2 hh = __halves2half2(h0, h1);
        __half2 ll = __floats2half2_rn(l0, l1);
        d_Whh[(size_t)m * WSZH + i] = *(uint32_t*)&hh;
        d_Wll[(size_t)m * WSZH + i] = *(uint32_t*)&ll;
    }
}

#define MMA_F16(d, a0, a1, a2, a3, b0, b1) \
    asm volatile( \
        "mma.sync.aligned.m16n8k16.row.col.f32.f16.f16.f32 " \
        "{%0,%1,%2,%3}, {%4,%5,%6,%7}, {%8,%9}, {%0,%1,%2,%3};" \
        : "+f"((d)[0]), "+f"((d)[1]), "+f"((d)[2]), "+f"((d)[3]) \
        : "r"(a0), "r"(a1), "r"(a2), "r"(a3), "r"(b0), "r"(b1))

#define LDSM_X4(r0, r1, r2, r3, addr) \
    asm volatile( \
        "ldmatrix.sync.aligned.m8n8.x4.shared.b16 {%0,%1,%2,%3}, [%4];" \
        : "=r"(r0), "=r"(r1), "=r"(r2), "=r"(r3) : "r"(addr))

// ---------------- GEMM tile device function (fp16, LDSM) ---------------------
// C[row, coloff+c] = act( A[row,:] @ W[c,:] + bias[c] ) for a BM x 128 tile.
// NPASS: 1 = Ah@Bh only; 2 = + Al@Bh (A-compensated); 3 = + Ah@Bl.
// smem half2-words, row stride 36 (== 4 mod 32: conflict-free LDSM phases).
#define KCH   64
#define STR   36

template <int WM, int NPASS>
__device__ __forceinline__ void gemm_tile(
    const float* __restrict__ Asrc, const int* __restrict__ gidx,
    const uint32_t* __restrict__ Wh, const uint32_t* __restrict__ Wl,
    const float* __restrict__ bias, float* __restrict__ C,
    int row0, int coloff, int do_relu, uint32_t* smx) {
    constexpr int BM = 32 * WM;
    constexpr int NAB = (NPASS >= 2) ? 2 : 1;   // # A buffers (hi[,lo])
    uint32_t* Ash = smx;
    uint32_t* Asl = smx + BM * STR;                       // valid iff NPASS>=2
    uint32_t* Bsh = smx + NAB * BM * STR;
    uint32_t* Bsl = smx + NAB * BM * STR + OUTD * STR;    // valid iff NPASS>=3
    __shared__ int rowidx[64];

    int t = threadIdx.x;
    if (t < BM) rowidx[t] = gidx ? gidx[row0 + t] : (row0 + t);
    __syncthreads();

    int wid = t >> 5, lane = t & 31;
    int wm = wid % WM;
    int wn = wid / WM;
    int qp = lane >> 2;
    int qi = lane & 3;
    constexpr int NT = 2 * WM;

    uint32_t ash32 = (uint32_t)__cvta_generic_to_shared(Ash);
    uint32_t asl32 = (uint32_t)__cvta_generic_to_shared(Asl);
    uint32_t bsh32 = (uint32_t)__cvta_generic_to_shared(Bsh);
    uint32_t bsl32 = (uint32_t)__cvta_generic_to_shared(Bsl);
    uint32_t aoffA[2], aoffB;
    #pragma unroll
    for (int mt = 0; mt < 2; mt++)
        aoffA[mt] = (uint32_t)(((wm * 32 + mt * 16 + (lane & 15)) * STR
                                + (lane >> 4) * 4) * 4);
    aoffB = (uint32_t)(((wn * (16 * WM) + (lane >> 4) * 8 + (lane & 7)) * STR
                        + ((lane >> 3) & 1) * 4) * 4);

    float acc[2][NT][4];
    #pragma unroll
    for (int mt = 0; mt < 2; mt++)
        #pragma unroll
        for (int nt = 0; nt < NT; nt++)
            #pragma unroll
            for (int j = 0; j < 4; j++) acc[mt][nt][j] = 0.f;

    for (int kc = 0; kc < 4; kc++) {
        #pragma unroll
        for (int i = 0; i < 2 * WM; i++) {
            int idx = t + i * 256;
            int r  = idx >> 4;
            int k4 = idx & 15;
            const float4 v = *(const float4*)(Asrc + (size_t)rowidx[r] * DFEAT
                                              + kc * KCH + k4 * 4);
            __half2 h01 = __floats2half2_rn(v.x, v.y);
            __half2 h23 = __floats2half2_rn(v.z, v.w);
            uint2 hw;
            hw.x = *(uint32_t*)&h01; hw.y = *(uint32_t*)&h23;
            *(uint2*)(Ash + r * STR + k4 * 2) = hw;
            if (NPASS >= 2) {
                float2 f01 = __half22float2(h01);
                float2 f23 = __half22float2(h23);
                __half2 l01 = __floats2half2_rn(v.x - f01.x, v.y - f01.y);
                __half2 l23 = __floats2half2_rn(v.z - f23.x, v.w - f23.y);
                uint2 lw;
                lw.x = *(uint32_t*)&l01; lw.y = *(uint32_t*)&l23;
                *(uint2*)(Asl + r * STR + k4 * 2) = lw;
            }
        }
        #pragma unroll
        for (int i = 0; i < 4; i++) {
            int idx = t + i * 256;
            int r  = idx >> 3;
            int w4 = idx & 7;
            *(uint4*)(Bsh + r * STR + w4 * 4) =
                *(const uint4*)(Wh + (size_t)r * (DFEAT / 2) + kc * (KCH / 2) + w4 * 4);
            if (NPASS >= 3)
                *(uint4*)(Bsl + r * STR + w4 * 4) =
                    *(const uint4*)(Wl + (size_t)r * (DFEAT / 2) + kc * (KCH / 2) + w4 * 4);
        }
        __syncthreads();

        #pragma unroll
        for (int kk2 = 0; kk2 < KCH / 2; kk2 += 8) {
            uint32_t kb = (uint32_t)(kk2 * 4);
            uint32_t ah[2][4], al[2][4];
            #pragma unroll
            for (int mt = 0; mt < 2; mt++) {
                LDSM_X4(ah[mt][0], ah[mt][1], ah[mt][2], ah[mt][3],
                        ash32 + aoffA[mt] + kb);
                if (NPASS >= 2)
                    LDSM_X4(al[mt][0], al[mt][1], al[mt][2], al[mt][3],
                            asl32 + aoffA[mt] + kb);
            }
            #pragma unroll
            for (int p = 0; p < WM; p++) {
                uint32_t pboff = aoffB + (uint32_t)(p * 16 * STR * 4);
                uint32_t bh0, bh1, bh2, bh3;
                LDSM_X4(bh0, bh1, bh2, bh3, bsh32 + pboff + kb);
                #pragma unroll
                for (int mt = 0; mt < 2; mt++) {
                    MMA_F16(acc[mt][2 * p],     ah[mt][0], ah[mt][1], ah[mt][2], ah[mt][3], bh0, bh1);
                    MMA_F16(acc[mt][2 * p + 1], ah[mt][0], ah[mt][1], ah[mt][2], ah[mt][3], bh2, bh3);
                    if (NPASS >= 2) {
                        MMA_F16(acc[mt][2 * p],     al[mt][0], al[mt][1], al[mt][2], al[mt][3], bh0, bh1);
                        MMA_F16(acc[mt][2 * p + 1], al[mt][0], al[mt][1], al[mt][2], al[mt][3], bh2, bh3);
                    }
                }
                if (NPASS >= 3) {
                    uint32_t bl0, bl1, bl2, bl3;
                    LDSM_X4(bl0, bl1, bl2, bl3, bsl32 + pboff + kb);
                    #pragma unroll
                    for (int mt = 0; mt < 2; mt++) {
                        MMA_F16(acc[mt][2 * p],     ah[mt][0], ah[mt][1], ah[mt][2], ah[mt][3], bl0, bl1);
                        MMA_F16(acc[mt][2 * p + 1], ah[mt][0], ah[mt][1], ah[mt][2], ah[mt][3], bl2, bl3);
                    }
                }
            }
        }
        __syncthreads();
    }

    #pragma unroll
    for (int nt = 0; nt < NT; nt++) {
        int col = wn * (16 * WM) + nt * 8 + 2 * qi;
        float bx2 = bias[col], by = bias[col + 1];
        #pragma unroll
        for (int mt = 0; mt < 2; mt++) {
            int r0 = row0 + wm * 32 + mt * 16 + qp;
            float v0 = acc[mt][nt][0] + bx2;
            float v1 = acc[mt][nt][1] + by;
            float v2 = acc[mt][nt][2] + bx2;
            float v3 = acc[mt][nt][3] + by;
            if (do_relu) {
                v0 = fmaxf(v0, 0.f); v1 = fmaxf(v1, 0.f);
                v2 = fmaxf(v2, 0.f); v3 = fmaxf(v3, 0.f);
            }
            *(float2*)(C + (size_t)r0 * (2 * OUTD) + coloff + col)       = make_float2(v0, v1);
            *(float2*)(C + (size_t)(r0 + 8) * (2 * OUTD) + coloff + col) = make_float2(v2, v3);
        }
    }
}

// ---- fused launch: x-branch layer-1 GEMM (1-pass) + all means
// blocks [0,400): z1 x-tiles | [400,416): z0 x-tiles | [416,544): mean25 -> m1
// | [544,3744): mean10 -> m2.
__global__ __launch_bounds__(256, 4)
void fused_x_means_kernel(const float* __restrict__ feats,
                          const int* __restrict__ ids,
                          const float* __restrict__ b1x) {
    extern __shared__ uint32_t smx[];
    int bx = blockIdx.x;
    if (bx < NBG_Z1) {
        gemm_tile<2, 1>(feats, d_ids1, d_Whh, d_Wll, b1x, d_z1,
                        bx * 64, 0, 1, smx);
    } else if (bx < NBG_Z1 + NBG_Z0) {
        gemm_tile<2, 1>(feats, ids, d_Whh, d_Wll, b1x, d_z0,
                        (bx - NBG_Z1) * 64, 0, 1, smx);
    } else if (bx < NBG_Z1 + NBG_Z0 + NB25) {
        mean_body8<FAN1>(feats, d_ids1, d_m1, bx - NBG_Z1 - NBG_Z0);
    } else {
        mean_body8<FAN2>(feats, d_ids2, d_m2, bx - NBG_Z1 - NBG_Z0 - NB25);
    }
}

// ---- n-branch layer-1 GEMM (consumes m2/m1; 1-pass)
__global__ __launch_bounds__(256, 4)
void l1_n_kernel(const float* __restrict__ b1n) {
    extern __shared__ uint32_t smx[];
    int bx = blockIdx.x;
    if (bx < NBG_Z1)
        gemm_tile<2, 1>(d_m2, nullptr, d_Whh + WSZH, d_Wll + WSZH, b1n, d_z1,
                        bx * 64, OUTD, 1, smx);
    else
        gemm_tile<2, 1>(d_m1, nullptr, d_Whh + WSZH, d_Wll + WSZH, b1n, d_z0,
                        (bx - NBG_Z1) * 64, OUTD, 1, smx);
}

// ---- merged m3 means + out-layer x-branch (both depend only on l1_n)
__global__ __launch_bounds__(256, 3)
void m3_outx_kernel(const float* __restrict__ b2x, float* __restrict__ out) {
    extern __shared__ uint32_t smx[];
    int bx = blockIdx.x;
    if (bx < NB25)
        mean_body8<FAN1>(d_z1, nullptr, d_m3, bx);
    else
        gemm_tile<1, 3>(d_z0, nullptr, d_Whh + 2 * WSZH, d_Wll + 2 * WSZH,
                        b2x, out, (bx - NB25) * 32, 0, 0, smx);
}

// ---- out-layer n-branch (consumes m3; fully compensated)
__global__ __launch_bounds__(256, 3)
void out_n_kernel(const float* __restrict__ b2n, float* __restrict__ out) {
    extern __shared__ uint32_t smx[];
    gemm_tile<1, 3>(d_m3, nullptr, d_Whh + 3 * WSZH, d_Wll + 3 * WSZH,
                    b2n, out, blockIdx.x * 32, OUTD, 0, smx);
}

// ---------------- host launcher ----------------
extern "C" void kernel_launch(void* const* d_in, const int* in_sizes, int n_in,
                              void* d_out, int out_size) {
    const int*   ids   = (const int*)d_in[0];
    const int*   adj   = (const int*)d_in[1];
    const float* feats = (const float*)d_in[2];
    const float* W1x   = (const float*)d_in[3];
    const float* b1x   = (const float*)d_in[4];
    const float* W1n   = (const float*)d_in[5];
    const float* b1n   = (const float*)d_in[6];
    const float* W2x   = (const float*)d_in[7];
    const float* b2x   = (const float*)d_in[8];
    const float* W2n   = (const float*)d_in[9];
    const float* b2n   = (const float*)d_in[10];
    float* out = (float*)d_out;

    // layer-1 (NPASS=1): Ash(64*36) + Bsh(128*36) words = 27648 B
    const int SMEM_L1  = (64 * STR + OUTD * STR) * 4;          // 27648 B
    const int SMEM_OUT = (2 * 32 * STR + 2 * OUTD * STR) * 4;  // 46080 B (NPASS=3)
    cudaFuncSetAttribute(fused_x_means_kernel,
                         cudaFuncAttributeMaxDynamicSharedMemorySize, SMEM_L1);
    cudaFuncSetAttribute(l1_n_kernel,
                         cudaFuncAttributeMaxDynamicSharedMemorySize, SMEM_L1);
    cudaFuncSetAttribute(m3_outx_kernel,
                         cudaFuncAttributeMaxDynamicSharedMemorySize, SMEM_OUT);
    cudaFuncSetAttribute(out_n_kernel,
                         cudaFuncAttributeMaxDynamicSharedMemorySize, SMEM_OUT);

    // 1. permutations (threefry, partitionable, bits1 ^ bits2)
    setup_perm_kernel<<<1, 128>>>();
    // 2. weight fp16 hi/lo split
    split_w_kernel<<<dim3(WSZH / 256, 4), 256>>>(W1x, W1n, W2x, W2n);
    // 3. neighbor id tables
    build_ids_kernel<<<(M1 + 255) / 256, 256>>>(ids, adj);
    // 4. FUSED: x-branch layer-1 GEMM (1-pass) + m1 + m2 means
    fused_x_means_kernel<<<NBG_Z1 + NBG_Z0 + NB25 + NB10, 256, SMEM_L1>>>(
        feats, ids, b1x);
    // 5. n-branch layer-1 GEMM (1-pass), consumes m2/m1
    l1_n_kernel<<<NBG_Z1 + NBG_Z0, 256, SMEM_L1>>>(b1n);
    // 6. MERGED: m3 = mean25(z1 groups) + out-layer x-branch (z0@W2x)
    m3_outx_kernel<<<NB25 + BATCH / 32, 256, SMEM_OUT>>>(b2x, out);
    // 7. out-layer n-branch: out cols [128,256) = m3@W2n + b2n
    out_n_kernel<<<BATCH / 32, 256, SMEM_OUT>>>(b2n, out);
}